// round 13
// baseline (speedup 1.0000x reference)
#include <cuda_runtime.h>
#include <cuda_fp16.h>
#include <cstdint>
#include <math.h>

// Problem constants
#define BB 4
#define CC 256
#define HH 64
#define WW 64
#define GG 4
#define HEADS 8
#define BH (BB*HEADS)  // 32
#define CG 64          // C/G
#define HC 32          // C/HEADS
#define HW (HH*WW)     // 4096
#define HK 32
#define WK 32
#define NS (HK*WK)     // 1024
#define SCALE_LOG2E 0.25501650770101956f   // HC^-0.5 * log2(e)

// Scratch (device globals; no runtime allocation allowed)
__device__ __half g_qc    [BB*CC*HW];   // q half [b][C][HW]
__device__ __half g_kh    [BB*CC*NS];
__device__ __half g_vh    [BB*CC*NS];
__device__ __half g_xs_h  [BB*CC*NS];
__device__ __half g_attn_h[BB*CC*HW];
__device__ float4 g_w4    [BB*GG*NS];   // bilinear weights (valid-folded)
__device__ int4   g_i4    [BB*GG*NS];   // clamped plane indices

// ---------------------------------------------------------------------------
__device__ __forceinline__ void cp16(void* s, const void* g)
{
    unsigned int saddr = (unsigned int)__cvta_generic_to_shared(s);
    asm volatile("cp.async.cg.shared.global [%0],[%1],16;" :: "r"(saddr), "l"(g));
}
__device__ __forceinline__ void cp_commit() { asm volatile("cp.async.commit_group;"); }
template<int N> __device__ __forceinline__ void cp_wait()
{ asm volatile("cp.async.wait_group %0;" :: "n"(N)); }

// ---------------------------------------------------------------------------
// fp16 TC GEMM with bias. BM=128, BN=64, BK=32; 8 warps = 4m x 2n, warp tile
// 32x32 (acc 32 regs). N-split doubles grid vs BN=128 with NO extra B traffic
// (A=weights redundancy is L2-served). MODE 0: fp32 out. MODE 1: half out.
// BF32: B operand fp32 converted inline. A is fp32 weights converted inline.
// ---------------------------------------------------------------------------
template <int MODE, bool BF32>
__device__ __forceinline__ void hgemm_body(
    const float* __restrict__ A,
    const void* __restrict__ BxV,
    const float*  __restrict__ bias,
    void* __restrict__ Yv,
    int N, int m0, int n0)
{
    __shared__ __half As[2][128][40];
    __shared__ __half Bs[2][32][72];

    const int tid  = threadIdx.x;
    const int lane = tid & 31;
    const int warp = tid >> 5;
    const int wm = warp & 3;     // 0..3 (32 rows each)
    const int wn = warp >> 2;    // 0..1 (32 cols each)

    float acc[2][4][4];
#pragma unroll
    for (int mt = 0; mt < 2; mt++)
#pragma unroll
        for (int nt = 0; nt < 4; nt++)
#pragma unroll
            for (int r = 0; r < 4; r++) acc[mt][nt][r] = 0.f;

    auto cvt8 = [](const float* src, uint4* dst) {
        float4 a = *reinterpret_cast<const float4*>(src);
        float4 b = *reinterpret_cast<const float4*>(src + 4);
        __half2 h[4];
        h[0] = __floats2half2_rn(a.x, a.y);
        h[1] = __floats2half2_rn(a.z, a.w);
        h[2] = __floats2half2_rn(b.x, b.y);
        h[3] = __floats2half2_rn(b.z, b.w);
        *dst = *reinterpret_cast<uint4*>(h);
    };

    // A tile 128x32 halves: 2 uint4 per thread (from fp32 weights)
    auto loadA = [&](int kt, uint4* pa) {
#pragma unroll
        for (int l = 0; l < 2; l++) {
            int lin = tid + l * 256;
            int r  = lin >> 2;
            int kg = (lin & 3) << 3;
            cvt8(&A[(size_t)(m0 + r) * CC + kt * 32 + kg], &pa[l]);
        }
    };
    // B tile 32x64 halves: 1 uint4 per thread
    auto loadB = [&](int kt, uint4* pb) {
        int r  = tid >> 3;            // 0..31
        int nn = (tid & 7) << 3;      // 0..56
        if (BF32) {
            cvt8((const float*)BxV + (size_t)(kt * 32 + r) * N + n0 + nn, pb);
        } else {
            *pb = *reinterpret_cast<const uint4*>(
                &((const __half*)BxV)[(size_t)(kt * 32 + r) * N + n0 + nn]);
        }
    };
    auto storeA = [&](int buf, uint4* pa) {
#pragma unroll
        for (int l = 0; l < 2; l++) {
            int lin = tid + l * 256;
            int r  = lin >> 2;
            int kg = (lin & 3) << 3;
            *reinterpret_cast<uint4*>(&As[buf][r][kg]) = pa[l];
        }
    };
    auto storeB = [&](int buf, uint4* pb) {
        int r  = tid >> 3;
        int nn = (tid & 7) << 3;
        *reinterpret_cast<uint4*>(&Bs[buf][r][nn]) = *pb;
    };

    {
        uint4 pa[2], pb[1];
        loadA(0, pa); loadB(0, pb);
        storeA(0, pa); storeB(0, pb);
    }
    __syncthreads();

    const int NKT = CC / 32;
    for (int kt = 0; kt < NKT; kt++) {
        const int cur = kt & 1;
        uint4 na[2], nb[1];
        if (kt + 1 < NKT) { loadA(kt + 1, na); loadB(kt + 1, nb); }

#pragma unroll
        for (int ks = 0; ks < 2; ks++) {
            unsigned int af[2][4];
#pragma unroll
            for (int mt = 0; mt < 2; mt++) {
                int row = wm * 32 + mt * 16 + (lane & 15);
                int col = ks * 16 + ((lane >> 4) << 3);
                unsigned int addr = (unsigned int)__cvta_generic_to_shared(&As[cur][row][col]);
                asm volatile("ldmatrix.sync.aligned.m8n8.x4.shared.b16 {%0,%1,%2,%3},[%4];"
                             : "=r"(af[mt][0]), "=r"(af[mt][1]), "=r"(af[mt][2]), "=r"(af[mt][3])
                             : "r"(addr));
            }
            unsigned int bf[4][2];
#pragma unroll
            for (int nt = 0; nt < 4; nt++) {
                int krow = ks * 16 + (lane & 15);
                int coln = wn * 32 + nt * 8;
                unsigned int addr = (unsigned int)__cvta_generic_to_shared(&Bs[cur][krow][coln]);
                asm volatile("ldmatrix.sync.aligned.m8n8.x2.trans.shared.b16 {%0,%1},[%2];"
                             : "=r"(bf[nt][0]), "=r"(bf[nt][1])
                             : "r"(addr));
            }
#pragma unroll
            for (int mt = 0; mt < 2; mt++)
#pragma unroll
                for (int nt = 0; nt < 4; nt++) {
                    asm volatile(
                        "mma.sync.aligned.m16n8k16.row.col.f32.f16.f16.f32 "
                        "{%0,%1,%2,%3},{%4,%5,%6,%7},{%8,%9},{%0,%1,%2,%3};"
                        : "+f"(acc[mt][nt][0]), "+f"(acc[mt][nt][1]),
                          "+f"(acc[mt][nt][2]), "+f"(acc[mt][nt][3])
                        : "r"(af[mt][0]), "r"(af[mt][1]), "r"(af[mt][2]), "r"(af[mt][3]),
                          "r"(bf[nt][0]), "r"(bf[nt][1]));
                }
        }

        if (kt + 1 < NKT) {
            storeA(cur ^ 1, na); storeB(cur ^ 1, nb);
            __syncthreads();
        }
    }

#pragma unroll
    for (int mt = 0; mt < 2; mt++) {
        int r0 = m0 + wm * 32 + mt * 16 + (lane >> 2);
        float b0 = bias[r0], b1 = bias[r0 + 8];
#pragma unroll
        for (int nt = 0; nt < 4; nt++) {
            int c = n0 + wn * 32 + nt * 8 + (lane & 3) * 2;
            float v0 = acc[mt][nt][0] + b0, v1 = acc[mt][nt][1] + b0;
            float v2 = acc[mt][nt][2] + b1, v3 = acc[mt][nt][3] + b1;
            if (MODE == 0) {
                float* Y = (float*)Yv;
                *reinterpret_cast<float2*>(&Y[(size_t)r0 * N + c])       = make_float2(v0, v1);
                *reinterpret_cast<float2*>(&Y[(size_t)(r0 + 8) * N + c]) = make_float2(v2, v3);
            } else {
                __half* Y = (__half*)Yv;
                *reinterpret_cast<__half2*>(&Y[(size_t)r0 * N + c])       = __floats2half2_rn(v0, v1);
                *reinterpret_cast<__half2*>(&Y[(size_t)(r0 + 8) * N + c]) = __floats2half2_rn(v2, v3);
            }
        }
    }
}

__global__ void __launch_bounds__(256) hgemm_qproj(
    const float* __restrict__ W, const float* __restrict__ X,
    const float* __restrict__ bias, __half* __restrict__ Y)
{
    hgemm_body<1, true>(W, X + (size_t)blockIdx.z * CC * HW, bias,
                        Y + (size_t)blockIdx.z * CC * HW, HW,
                        blockIdx.y * 128, blockIdx.x * 64);
}

__global__ void __launch_bounds__(256) hgemm_oproj(
    const float* __restrict__ W, const __half* __restrict__ X,
    const float* __restrict__ bias, float* __restrict__ Y)
{
    hgemm_body<0, false>(W, X + (size_t)blockIdx.z * CC * HW, bias,
                         Y + (size_t)blockIdx.z * CC * HW, HW,
                         blockIdx.y * 128, blockIdx.x * 64);
}

__global__ void __launch_bounds__(256) hgemm_kv_h(
    const float* __restrict__ Wk, const float* __restrict__ Wv,
    const float* __restrict__ bk, const float* __restrict__ bv,
    const __half* __restrict__ X, __half* __restrict__ Yk, __half* __restrict__ Yv)
{
    int z = blockIdx.z;
    int b = z >> 1;
    bool isv = z & 1;
    hgemm_body<1, false>(isv ? Wv : Wk, X + (size_t)b * CC * NS, isv ? bv : bk,
                         (isv ? Yv : Yk) + (size_t)b * CC * NS, NS,
                         blockIdx.y * 128, blockIdx.x * 64);
}

// ---------------------------------------------------------------------------
// Offset field: dwconv + LN + GELU + pointwise + tanh -> bilinear meta.
// ---------------------------------------------------------------------------
__global__ void __launch_bounds__(256) offset_field_kernel(
    const __half* __restrict__ qc,
    const float* __restrict__ dw_w, const float* __restrict__ dw_b,
    const float* __restrict__ ln_g, const float* __restrict__ ln_b,
    const float* __restrict__ pw_w,
    float4* __restrict__ w4, int4* __restrict__ i4)
{
    __shared__ float rows[3 * CG * WW];   // 48KB exactly; reused as reduction buf
    float* red = rows;                    // [8][33]: red[tg*33 + wo]

    const int ho = blockIdx.x;
    const int bg = blockIdx.y;
    const int b = bg >> 2, g = bg & 3;
    const int tid = threadIdx.x;
    const int iy0 = ho * 2 - 1;

    const __half* qbase = qc + (size_t)(b * CC + g * CG) * HW;
#pragma unroll
    for (int l = 0; l < 6; l++) {
        int lin = (tid + l * 256) * 8;
        int r   = lin >> 12;
        int rem = lin & 4095;
        int cg  = rem >> 6;
        int w   = rem & 63;
        int iy  = iy0 + r;
        if ((unsigned)iy < (unsigned)HH) {
            uint4 hv = *reinterpret_cast<const uint4*>(&qbase[(size_t)cg * HW + iy * WW + w]);
            const __half2* hp = reinterpret_cast<const __half2*>(&hv);
#pragma unroll
            for (int j = 0; j < 4; j++) {
                float2 f = __half22float2(hp[j]);
                rows[lin + 2*j]     = f.x;
                rows[lin + 2*j + 1] = f.y;
            }
        } else {
#pragma unroll
            for (int j = 0; j < 8; j++) rows[lin + j] = 0.f;
        }
    }
    __syncthreads();

    const int wo = tid & 31;
    const int tg = tid >> 5;
    const int ix0 = wo * 2 - 1;

    float conv[8];
#pragma unroll
    for (int j = 0; j < 8; j++) {
        int cg = tg * 8 + j;
        float a = dw_b[cg];
#pragma unroll
        for (int ky = 0; ky < 3; ky++) {
#pragma unroll
            for (int kx = 0; kx < 3; kx++) {
                int ix = ix0 + kx;
                if ((unsigned)ix < (unsigned)WW)
                    a += rows[ky * 4096 + cg * 64 + ix] * dw_w[cg * 9 + ky * 3 + kx];
            }
        }
        conv[j] = a;
    }
    __syncthreads();

    float s = 0.f;
#pragma unroll
    for (int j = 0; j < 8; j++) s += conv[j];
    red[tg * 33 + wo] = s;
    __syncthreads();
    float mu = 0.f;
#pragma unroll
    for (int t = 0; t < 8; t++) mu += red[t * 33 + wo];
    mu *= (1.f / 64.f);
    __syncthreads();

    float s2 = 0.f;
#pragma unroll
    for (int j = 0; j < 8; j++) { float d = conv[j] - mu; s2 += d * d; }
    red[tg * 33 + wo] = s2;
    __syncthreads();
    float var = 0.f;
#pragma unroll
    for (int t = 0; t < 8; t++) var += red[t * 33 + wo];
    var *= (1.f / 64.f);
    float rstd = rsqrtf(var + 1e-5f);
    __syncthreads();

    float p0p = 0.f, p1p = 0.f;
#pragma unroll
    for (int j = 0; j < 8; j++) {
        int cg = tg * 8 + j;
        float y  = (conv[j] - mu) * rstd * ln_g[cg] + ln_b[cg];
        float ge = 0.5f * y * (1.f + erff(y * 0.70710678118654752f));
        p0p += ge * pw_w[cg];
        p1p += ge * pw_w[CG + cg];
    }
    red[tg * 33 + wo] = p0p;
    __syncthreads();
    float p0 = 0.f;
#pragma unroll
    for (int t = 0; t < 8; t++) p0 += red[t * 33 + wo];
    __syncthreads();
    red[tg * 33 + wo] = p1p;
    __syncthreads();
    if (tg == 0) {
        float p1 = 0.f;
#pragma unroll
        for (int t = 0; t < 8; t++) p1 += red[t * 33 + wo];

        float offy = tanhf(p0) * (2.0f / (float)HK);
        float offx = tanhf(p1) * (2.0f / (float)WK);
        float ref_y = (0.5f + (float)ho) * (2.f / (HK - 1.f)) - 1.f;
        float ref_x = (0.5f + (float)wo) * (2.f / (WK - 1.f)) - 1.f;
        float gx = ((offx + ref_x) + 1.f) * 0.5f * (WW - 1);
        float gy = ((offy + ref_y) + 1.f) * 0.5f * (HH - 1);

        float x0f = floorf(gx), y0f = floorf(gy);
        float wx = gx - x0f, wy = gy - y0f;
        int x0 = (int)x0f, y0 = (int)y0f;
        int x1 = x0 + 1, y1 = y0 + 1;
        float vx0 = (x0 >= 0 && x0 <= WW-1) ? 1.f : 0.f;
        float vx1 = (x1 >= 0 && x1 <= WW-1) ? 1.f : 0.f;
        float vy0 = (y0 >= 0 && y0 <= HH-1) ? 1.f : 0.f;
        float vy1 = (y1 >= 0 && y1 <= HH-1) ? 1.f : 0.f;
        int x0c = min(max(x0, 0), WW-1), x1c = min(max(x1, 0), WW-1);
        int y0c = min(max(y0, 0), HH-1), y1c = min(max(y1, 0), HH-1);

        float4 w;
        w.x = (1.f - wx) * (1.f - wy) * vx0 * vy0;
        w.y = wx * (1.f - wy) * vx1 * vy0;
        w.z = (1.f - wx) * wy * vx0 * vy1;
        w.w = wx * wy * vx1 * vy1;
        int4 id;
        id.x = y0c * WW + x0c; id.y = y0c * WW + x1c;
        id.z = y1c * WW + x0c; id.w = y1c * WW + x1c;

        size_t sIdx = (size_t)bg * NS + ho * WK + wo;
        w4[sIdx] = w;
        i4[sIdx] = id;
    }
}

// ---------------------------------------------------------------------------
// Bilinear sampling from precomputed meta.
// ---------------------------------------------------------------------------
__global__ void __launch_bounds__(256) sample_kernel(
    const float* __restrict__ feat,
    const float4* __restrict__ w4, const int4* __restrict__ i4,
    __half* __restrict__ xs)
{
    __shared__ float plane[HW];        // 16KB

    const int cg = blockIdx.x;
    const int bg = blockIdx.y;
    const int b = bg >> 2, g = bg & 3;
    const int tid = threadIdx.x;

    const float* fc = feat + (size_t)(b * CC + g * CG + cg) * HW;
#pragma unroll
    for (int l = 0; l < 4; l++) {
        int i = (tid + l * 256) * 4;
        *reinterpret_cast<float4*>(&plane[i]) = *reinterpret_cast<const float4*>(&fc[i]);
    }
    __syncthreads();

    const float4* wb = w4 + (size_t)bg * NS;
    const int4*   ib = i4 + (size_t)bg * NS;
    __half* xbase = &xs[(size_t)(bg * CG + cg) * NS];
#pragma unroll
    for (int i = 0; i < 4; i++) {
        int s = tid + i * 256;
        float4 w = wb[s];
        int4  id = ib[s];
        float acc = w.x * plane[id.x] + w.y * plane[id.y]
                  + w.z * plane[id.z] + w.w * plane[id.w];
        xbase[s] = __float2half_rn(acc);
    }
}

// ---------------------------------------------------------------------------
// Tensor-core flash attention (R10 version). Q read channel-major via trans
// ldmatrix; scale on Q fragments. cp.async double-buffered K/V.
// ---------------------------------------------------------------------------
__global__ void __launch_bounds__(256) attn_mma_kernel(
    const __half* __restrict__ qc, const __half* __restrict__ kh,
    const __half* __restrict__ vh, __half* __restrict__ out)
{
    __shared__ __half Qb[5120];          // [32][136] Q in; [128][40] O out
    __shared__ __half Ks[2][32][72];
    __shared__ __half Vs[2][32][72];

    const int tid  = threadIdx.x;
    const int lane = tid & 31;
    const int warp = tid >> 5;
    const int bh = blockIdx.y;
    const int b = bh >> 3, h = bh & 7;
    const int m0 = blockIdx.x * 128;

    const __half* qbase = qc + (size_t)(b * CC + h * HC) * HW;
    const __half* kbase = kh + (size_t)(b * CC + h * HC) * NS;
    const __half* vbase = vh + (size_t)(b * CC + h * HC) * NS;

    const int sc = tid >> 3;
    const int snn = (tid & 7) * 8;
    auto stage = [&](int chunk, int buf) {
        int n0 = chunk * 64;
        cp16(&Ks[buf][sc][snn], &kbase[(size_t)sc * NS + n0 + snn]);
        cp16(&Vs[buf][sc][snn], &vbase[(size_t)sc * NS + n0 + snn]);
    };

    stage(0, 0); cp_commit();

    {
        int row = tid >> 3;
        int col = (tid & 7) * 16;
        const __half* src = &qbase[(size_t)row * HW + m0 + col];
        *reinterpret_cast<uint4*>(&Qb[row * 136 + col])     = *reinterpret_cast<const uint4*>(src);
        *reinterpret_cast<uint4*>(&Qb[row * 136 + col + 8]) = *reinterpret_cast<const uint4*>(src + 8);
    }
    __syncthreads();

    unsigned int qf[2][4];
    {
        int c_sub = ((lane >> 4) << 3) + (lane & 7);
        int m_sub = ((lane >> 3) & 1) << 3;
#pragma unroll
        for (int ks = 0; ks < 2; ks++) {
            unsigned int addr = (unsigned int)__cvta_generic_to_shared(
                &Qb[(ks * 16 + c_sub) * 136 + warp * 16 + m_sub]);
            asm volatile("ldmatrix.sync.aligned.m8n8.x4.trans.shared.b16 {%0,%1,%2,%3},[%4];"
                         : "=r"(qf[ks][0]), "=r"(qf[ks][1]), "=r"(qf[ks][2]), "=r"(qf[ks][3])
                         : "r"(addr));
        }
        __half2 sc2 = __float2half2_rn(SCALE_LOG2E);
#pragma unroll
        for (int ks = 0; ks < 2; ks++)
#pragma unroll
            for (int r = 0; r < 4; r++) {
                __half2 v = *reinterpret_cast<__half2*>(&qf[ks][r]);
                v = __hmul2(v, sc2);
                qf[ks][r] = *reinterpret_cast<unsigned int*>(&v);
            }
    }

    float o[4][4];
#pragma unroll
    for (int cf = 0; cf < 4; cf++)
#pragma unroll
        for (int r = 0; r < 4; r++) o[cf][r] = 0.f;
    float d0 = 0.f, d1 = 0.f;

    const int NC = NS / 64;
    for (int chunk = 0; chunk < NC; chunk++) {
        const int buf = chunk & 1;
        if (chunk + 1 < NC) { stage(chunk + 1, buf ^ 1); cp_commit(); cp_wait<1>(); }
        else                { cp_wait<0>(); }
        __syncthreads();

        float sf[8][4];
#pragma unroll
        for (int nf = 0; nf < 8; nf++)
#pragma unroll
            for (int r = 0; r < 4; r++) sf[nf][r] = 0.f;
#pragma unroll
        for (int ks = 0; ks < 2; ks++) {
#pragma unroll
            for (int ng = 0; ng < 4; ng++) {
                unsigned int b0, b1, b2, b3;
                unsigned int addr = (unsigned int)__cvta_generic_to_shared(
                    &Ks[buf][ks * 16 + (lane & 15)][ng * 16 + ((lane >> 4) << 3)]);
                asm volatile("ldmatrix.sync.aligned.m8n8.x4.trans.shared.b16 {%0,%1,%2,%3},[%4];"
                             : "=r"(b0), "=r"(b1), "=r"(b2), "=r"(b3) : "r"(addr));
                asm volatile(
                    "mma.sync.aligned.m16n8k16.row.col.f32.f16.f16.f32 "
                    "{%0,%1,%2,%3},{%4,%5,%6,%7},{%8,%9},{%0,%1,%2,%3};"
                    : "+f"(sf[2*ng][0]), "+f"(sf[2*ng][1]), "+f"(sf[2*ng][2]), "+f"(sf[2*ng][3])
                    : "r"(qf[ks][0]), "r"(qf[ks][1]), "r"(qf[ks][2]), "r"(qf[ks][3]),
                      "r"(b0), "r"(b1));
                asm volatile(
                    "mma.sync.aligned.m16n8k16.row.col.f32.f16.f16.f32 "
                    "{%0,%1,%2,%3},{%4,%5,%6,%7},{%8,%9},{%0,%1,%2,%3};"
                    : "+f"(sf[2*ng+1][0]), "+f"(sf[2*ng+1][1]), "+f"(sf[2*ng+1][2]), "+f"(sf[2*ng+1][3])
                    : "r"(qf[ks][0]), "r"(qf[ks][1]), "r"(qf[ks][2]), "r"(qf[ks][3]),
                      "r"(b2), "r"(b3));
            }
        }

        unsigned int pa[4][4];
#pragma unroll
        for (int j = 0; j < 4; j++) {
            float e0 = exp2f(sf[2*j][0]);
            float e1 = exp2f(sf[2*j][1]);
            float e2 = exp2f(sf[2*j][2]);
            float e3 = exp2f(sf[2*j][3]);
            float f0 = exp2f(sf[2*j+1][0]);
            float f1 = exp2f(sf[2*j+1][1]);
            float f2 = exp2f(sf[2*j+1][2]);
            float f3 = exp2f(sf[2*j+1][3]);
            d0 += (e0 + e1) + (f0 + f1);
            d1 += (e2 + e3) + (f2 + f3);
            __half2 h0 = __floats2half2_rn(e0, e1);
            __half2 h1 = __floats2half2_rn(e2, e3);
            __half2 h2 = __floats2half2_rn(f0, f1);
            __half2 h3 = __floats2half2_rn(f2, f3);
            pa[j][0] = *reinterpret_cast<unsigned int*>(&h0);
            pa[j][1] = *reinterpret_cast<unsigned int*>(&h1);
            pa[j][2] = *reinterpret_cast<unsigned int*>(&h2);
            pa[j][3] = *reinterpret_cast<unsigned int*>(&h3);
        }

#pragma unroll
        for (int ks2 = 0; ks2 < 4; ks2++) {
#pragma unroll
            for (int cg2 = 0; cg2 < 2; cg2++) {
                unsigned int b0, b1, b2, b3;
                unsigned int addr = (unsigned int)__cvta_generic_to_shared(
                    &Vs[buf][cg2 * 16 + ((lane >> 4) << 3) + (lane & 7)]
                            [ks2 * 16 + ((lane >> 3) & 1) * 8]);
                asm volatile("ldmatrix.sync.aligned.m8n8.x4.shared.b16 {%0,%1,%2,%3},[%4];"
                             : "=r"(b0), "=r"(b1), "=r"(b2), "=r"(b3) : "r"(addr));
                asm volatile(
                    "mma.sync.aligned.m16n8k16.row.col.f32.f16.f16.f32 "
                    "{%0,%1,%2,%3},{%4,%5,%6,%7},{%8,%9},{%0,%1,%2,%3};"
                    : "+f"(o[2*cg2][0]), "+f"(o[2*cg2][1]), "+f"(o[2*cg2][2]), "+f"(o[2*cg2][3])
                    : "r"(pa[ks2][0]), "r"(pa[ks2][1]), "r"(pa[ks2][2]), "r"(pa[ks2][3]),
                      "r"(b0), "r"(b1));
                asm volatile(
                    "mma.sync.aligned.m16n8k16.row.col.f32.f16.f16.f32 "
                    "{%0,%1,%2,%3},{%4,%5,%6,%7},{%8,%9},{%0,%1,%2,%3};"
                    : "+f"(o[2*cg2+1][0]), "+f"(o[2*cg2+1][1]), "+f"(o[2*cg2+1][2]), "+f"(o[2*cg2+1][3])
                    : "r"(pa[ks2][0]), "r"(pa[ks2][1]), "r"(pa[ks2][2]), "r"(pa[ks2][3]),
                      "r"(b2), "r"(b3));
            }
        }
        __syncthreads();
    }

    d0 += __shfl_xor_sync(0xffffffffu, d0, 1);
    d0 += __shfl_xor_sync(0xffffffffu, d0, 2);
    d1 += __shfl_xor_sync(0xffffffffu, d1, 1);
    d1 += __shfl_xor_sync(0xffffffffu, d1, 2);
    float inv0 = 1.f / d0, inv1 = 1.f / d1;

    __syncthreads();
#pragma unroll
    for (int cf = 0; cf < 4; cf++) {
        int r = warp * 16 + (lane >> 2);
        int c = cf * 8 + (lane & 3) * 2;
        *reinterpret_cast<__half2*>(&Qb[r * 40 + c]) =
            __floats2half2_rn(o[cf][0] * inv0, o[cf][1] * inv0);
        *reinterpret_cast<__half2*>(&Qb[(r + 8) * 40 + c]) =
            __floats2half2_rn(o[cf][2] * inv1, o[cf][3] * inv1);
    }
    __syncthreads();

    {
        int c  = tid >> 3;
        int mb = (tid & 7) * 16;
        __half tmp[16];
#pragma unroll
        for (int j = 0; j < 16; j++) tmp[j] = Qb[(mb + j) * 40 + c];
        __half* dst = &out[((size_t)(b * CC + h * HC + c)) * HW + m0 + mb];
        *reinterpret_cast<uint4*>(dst)     = *reinterpret_cast<uint4*>(&tmp[0]);
        *reinterpret_cast<uint4*>(dst + 8) = *reinterpret_cast<uint4*>(&tmp[8]);
    }
}

// ---------------------------------------------------------------------------
extern "C" void kernel_launch(void* const* d_in, const int* in_sizes, int n_in,
                              void* d_out, int out_size)
{
    (void)in_sizes; (void)n_in; (void)out_size;
    const float* feat = (const float*)d_in[1];
    const float* dw_w = (const float*)d_in[2];
    const float* dw_b = (const float*)d_in[3];
    const float* lng  = (const float*)d_in[4];
    const float* lnb  = (const float*)d_in[5];
    const float* pw   = (const float*)d_in[6];
    const float* qw   = (const float*)d_in[7];
    const float* qb   = (const float*)d_in[8];
    const float* kw   = (const float*)d_in[9];
    const float* kb   = (const float*)d_in[10];
    const float* vw   = (const float*)d_in[11];
    const float* vb   = (const float*)d_in[12];
    const float* ow   = (const float*)d_in[13];
    const float* ob   = (const float*)d_in[14];
    float* out = (float*)d_out;

    float4* gw4; int4* gi4;
    __half *gqc, *gkh, *gvh, *gxsh, *gah;
    cudaGetSymbolAddress((void**)&gqc, g_qc);
    cudaGetSymbolAddress((void**)&gw4, g_w4);
    cudaGetSymbolAddress((void**)&gi4, g_i4);
    cudaGetSymbolAddress((void**)&gkh, g_kh);
    cudaGetSymbolAddress((void**)&gvh, g_vh);
    cudaGetSymbolAddress((void**)&gxsh, g_xs_h);
    cudaGetSymbolAddress((void**)&gah, g_attn_h);

    // 1) q projection (BN=64: 512 blocks)
    hgemm_qproj<<<dim3(HW/64, CC/128, BB), 256>>>(qw, feat, qb, gqc);
    // 2) offset field (bilinear meta) then sampling
    offset_field_kernel<<<dim3(HK, BB*GG), 256>>>(gqc, dw_w, dw_b, lng, lnb, pw, gw4, gi4);
    sample_kernel<<<dim3(CG, BB*GG), 256>>>(feat, gw4, gi4, gxsh);
    // 3) k, v projections (256 blocks)
    hgemm_kv_h<<<dim3(NS/64, CC/128, BB*2), 256>>>(kw, vw, kb, vb, gxsh, gkh, gvh);
    // 4) tensor-core flash attention (R10 version)
    attn_mma_kernel<<<dim3(HW/128, BH), 256>>>(gqc, gkh, gvh, gah);
    // 5) output projection (512 blocks)
    hgemm_oproj<<<dim3(HW/64, CC/128, BB), 256>>>(ow, gah, ob, out);
}

// round 14
// speedup vs baseline: 1.1067x; 1.1067x over previous
#include <cuda_runtime.h>
#include <cuda_fp16.h>
#include <cstdint>
#include <math.h>

// Problem constants
#define BB 4
#define CC 256
#define HH 64
#define WW 64
#define GG 4
#define HEADS 8
#define BH (BB*HEADS)  // 32
#define CG 64          // C/G
#define HC 32          // C/HEADS
#define HW (HH*WW)     // 4096
#define HK 32
#define WK 32
#define NS (HK*WK)     // 1024
#define SCALE_LOG2E 0.25501650770101956f   // HC^-0.5 * log2(e)

// Scratch (device globals; no runtime allocation allowed)
__device__ __half g_qc    [BB*CC*HW];   // q half [b][C][HW]
__device__ __half g_kh    [BB*CC*NS];
__device__ __half g_vh    [BB*CC*NS];
__device__ __half g_xs_h  [BB*CC*NS];
__device__ __half g_attn_h[BB*CC*HW];
__device__ float4 g_w4    [BB*GG*NS];   // bilinear weights (valid-folded)
__device__ int4   g_i4    [BB*GG*NS];   // clamped plane indices

// ---------------------------------------------------------------------------
__device__ __forceinline__ void cp16(void* s, const void* g)
{
    unsigned int saddr = (unsigned int)__cvta_generic_to_shared(s);
    asm volatile("cp.async.cg.shared.global [%0],[%1],16;" :: "r"(saddr), "l"(g));
}
__device__ __forceinline__ void cp_commit() { asm volatile("cp.async.commit_group;"); }
template<int N> __device__ __forceinline__ void cp_wait()
{ asm volatile("cp.async.wait_group %0;" :: "n"(N)); }

// ---------------------------------------------------------------------------
// fp16 TC GEMM with bias (R10 shape: BM=128, BN=128, BK=32) with PREFETCH
// DISTANCE 2: two register sets; loads for kt+3 issue during iter kt and are
// consumed at iter kt+2, doubling the latency budget per k-iteration.
// MODE 0: fp32 out. MODE 1: half out. BF32: B operand fp32 converted inline.
// A operand is fp32 weights, converted inline.
// ---------------------------------------------------------------------------
template <int MODE, bool BF32>
__device__ __forceinline__ void hgemm_body(
    const float* __restrict__ A,
    const void* __restrict__ BxV,
    const float*  __restrict__ bias,
    void* __restrict__ Yv,
    int N, int m0, int n0)
{
    __shared__ __half As[2][128][40];
    __shared__ __half Bs[2][32][136];

    const int tid  = threadIdx.x;
    const int lane = tid & 31;
    const int warp = tid >> 5;
    const int wm = warp & 1;
    const int wn = warp >> 1;

    float acc[4][4][4];
#pragma unroll
    for (int mt = 0; mt < 4; mt++)
#pragma unroll
        for (int nt = 0; nt < 4; nt++)
#pragma unroll
            for (int r = 0; r < 4; r++) acc[mt][nt][r] = 0.f;

    auto cvt8 = [](const float* src, uint4* dst) {
        float4 a = *reinterpret_cast<const float4*>(src);
        float4 b = *reinterpret_cast<const float4*>(src + 4);
        __half2 h[4];
        h[0] = __floats2half2_rn(a.x, a.y);
        h[1] = __floats2half2_rn(a.z, a.w);
        h[2] = __floats2half2_rn(b.x, b.y);
        h[3] = __floats2half2_rn(b.z, b.w);
        *dst = *reinterpret_cast<uint4*>(h);
    };

    auto loadA = [&](int kt, uint4* pa) {
#pragma unroll
        for (int l = 0; l < 2; l++) {
            int lin = tid + l * 256;
            int r  = lin >> 2;
            int kg = (lin & 3) << 3;
            cvt8(&A[(size_t)(m0 + r) * CC + kt * 32 + kg], &pa[l]);
        }
    };
    auto loadB = [&](int kt, uint4* pb) {
#pragma unroll
        for (int l = 0; l < 2; l++) {
            int lin = tid + l * 256;
            int r  = lin >> 4;
            int nn = (lin & 15) << 3;
            if (BF32) {
                cvt8((const float*)BxV + (size_t)(kt * 32 + r) * N + n0 + nn, &pb[l]);
            } else {
                pb[l] = *reinterpret_cast<const uint4*>(
                    &((const __half*)BxV)[(size_t)(kt * 32 + r) * N + n0 + nn]);
            }
        }
    };
    auto storeA = [&](int buf, uint4* pa) {
#pragma unroll
        for (int l = 0; l < 2; l++) {
            int lin = tid + l * 256;
            int r  = lin >> 2;
            int kg = (lin & 3) << 3;
            *reinterpret_cast<uint4*>(&As[buf][r][kg]) = pa[l];
        }
    };
    auto storeB = [&](int buf, uint4* pb) {
#pragma unroll
        for (int l = 0; l < 2; l++) {
            int lin = tid + l * 256;
            int r  = lin >> 4;
            int nn = (lin & 15) << 3;
            *reinterpret_cast<uint4*>(&Bs[buf][r][nn]) = pb[l];
        }
    };

    const int NKT = CC / 32;   // 8
    // two register prefetch sets, distance-2 pipeline
    uint4 pa[2][2], pb[2][2];
    loadA(0, pa[0]); loadB(0, pb[0]);
    storeA(0, pa[0]); storeB(0, pb[0]);
    loadA(1, pa[1]); loadB(1, pb[1]);       // for kt=1 (stored at end of kt=0)
    loadA(2, pa[0]); loadB(2, pb[0]);       // for kt=2 (stored at end of kt=1)
    __syncthreads();

    for (int kt = 0; kt < NKT; kt++) {
        const int cur = kt & 1;

#pragma unroll
        for (int ks = 0; ks < 2; ks++) {
            unsigned int af[4][4];
#pragma unroll
            for (int mt = 0; mt < 4; mt++) {
                int row = wm * 64 + mt * 16 + (lane & 15);
                int col = ks * 16 + ((lane >> 4) << 3);
                unsigned int addr = (unsigned int)__cvta_generic_to_shared(&As[cur][row][col]);
                asm volatile("ldmatrix.sync.aligned.m8n8.x4.shared.b16 {%0,%1,%2,%3},[%4];"
                             : "=r"(af[mt][0]), "=r"(af[mt][1]), "=r"(af[mt][2]), "=r"(af[mt][3])
                             : "r"(addr));
            }
            unsigned int bf[4][2];
#pragma unroll
            for (int nt = 0; nt < 4; nt++) {
                int krow = ks * 16 + (lane & 15);
                int coln = wn * 32 + nt * 8;
                unsigned int addr = (unsigned int)__cvta_generic_to_shared(&Bs[cur][krow][coln]);
                asm volatile("ldmatrix.sync.aligned.m8n8.x2.trans.shared.b16 {%0,%1},[%2];"
                             : "=r"(bf[nt][0]), "=r"(bf[nt][1])
                             : "r"(addr));
            }
#pragma unroll
            for (int mt = 0; mt < 4; mt++)
#pragma unroll
                for (int nt = 0; nt < 4; nt++) {
                    asm volatile(
                        "mma.sync.aligned.m16n8k16.row.col.f32.f16.f16.f32 "
                        "{%0,%1,%2,%3},{%4,%5,%6,%7},{%8,%9},{%0,%1,%2,%3};"
                        : "+f"(acc[mt][nt][0]), "+f"(acc[mt][nt][1]),
                          "+f"(acc[mt][nt][2]), "+f"(acc[mt][nt][3])
                        : "r"(af[mt][0]), "r"(af[mt][1]), "r"(af[mt][2]), "r"(af[mt][3]),
                          "r"(bf[nt][0]), "r"(bf[nt][1]));
                }
        }

        if (kt + 1 < NKT) {
            const int ns = (kt + 1) & 1;    // reg set holding data for kt+1
            storeA(ns, pa[ns]); storeB(ns, pb[ns]);
            if (kt + 3 < NKT) { loadA(kt + 3, pa[ns]); loadB(kt + 3, pb[ns]); }
            __syncthreads();
        }
    }

#pragma unroll
    for (int mt = 0; mt < 4; mt++) {
        int r0 = m0 + wm * 64 + mt * 16 + (lane >> 2);
        float b0 = bias[r0], b1 = bias[r0 + 8];
#pragma unroll
        for (int nt = 0; nt < 4; nt++) {
            int c = n0 + wn * 32 + nt * 8 + (lane & 3) * 2;
            float v0 = acc[mt][nt][0] + b0, v1 = acc[mt][nt][1] + b0;
            float v2 = acc[mt][nt][2] + b1, v3 = acc[mt][nt][3] + b1;
            if (MODE == 0) {
                float* Y = (float*)Yv;
                *reinterpret_cast<float2*>(&Y[(size_t)r0 * N + c])       = make_float2(v0, v1);
                *reinterpret_cast<float2*>(&Y[(size_t)(r0 + 8) * N + c]) = make_float2(v2, v3);
            } else {
                __half* Y = (__half*)Yv;
                *reinterpret_cast<__half2*>(&Y[(size_t)r0 * N + c])       = __floats2half2_rn(v0, v1);
                *reinterpret_cast<__half2*>(&Y[(size_t)(r0 + 8) * N + c]) = __floats2half2_rn(v2, v3);
            }
        }
    }
}

__global__ void __launch_bounds__(256) hgemm_qproj(
    const float* __restrict__ W, const float* __restrict__ X,
    const float* __restrict__ bias, __half* __restrict__ Y)
{
    hgemm_body<1, true>(W, X + (size_t)blockIdx.z * CC * HW, bias,
                        Y + (size_t)blockIdx.z * CC * HW, HW,
                        blockIdx.y * 128, blockIdx.x * 128);
}

__global__ void __launch_bounds__(256) hgemm_oproj(
    const float* __restrict__ W, const __half* __restrict__ X,
    const float* __restrict__ bias, float* __restrict__ Y)
{
    hgemm_body<0, false>(W, X + (size_t)blockIdx.z * CC * HW, bias,
                         Y + (size_t)blockIdx.z * CC * HW, HW,
                         blockIdx.y * 128, blockIdx.x * 128);
}

__global__ void __launch_bounds__(256) hgemm_kv_h(
    const float* __restrict__ Wk, const float* __restrict__ Wv,
    const float* __restrict__ bk, const float* __restrict__ bv,
    const __half* __restrict__ X, __half* __restrict__ Yk, __half* __restrict__ Yv)
{
    int z = blockIdx.z;
    int b = z >> 1;
    bool isv = z & 1;
    hgemm_body<1, false>(isv ? Wv : Wk, X + (size_t)b * CC * NS, isv ? bv : bk,
                         (isv ? Yv : Yk) + (size_t)b * CC * NS, NS,
                         blockIdx.y * 128, blockIdx.x * 128);
}

// ---------------------------------------------------------------------------
// Offset field: dwconv + LN + GELU + pointwise + tanh -> bilinear meta.
// ---------------------------------------------------------------------------
__global__ void __launch_bounds__(256) offset_field_kernel(
    const __half* __restrict__ qc,
    const float* __restrict__ dw_w, const float* __restrict__ dw_b,
    const float* __restrict__ ln_g, const float* __restrict__ ln_b,
    const float* __restrict__ pw_w,
    float4* __restrict__ w4, int4* __restrict__ i4)
{
    __shared__ float rows[3 * CG * WW];   // 48KB exactly; reused as reduction buf
    float* red = rows;                    // [8][33]: red[tg*33 + wo]

    const int ho = blockIdx.x;
    const int bg = blockIdx.y;
    const int b = bg >> 2, g = bg & 3;
    const int tid = threadIdx.x;
    const int iy0 = ho * 2 - 1;

    const __half* qbase = qc + (size_t)(b * CC + g * CG) * HW;
#pragma unroll
    for (int l = 0; l < 6; l++) {
        int lin = (tid + l * 256) * 8;
        int r   = lin >> 12;
        int rem = lin & 4095;
        int cg  = rem >> 6;
        int w   = rem & 63;
        int iy  = iy0 + r;
        if ((unsigned)iy < (unsigned)HH) {
            uint4 hv = *reinterpret_cast<const uint4*>(&qbase[(size_t)cg * HW + iy * WW + w]);
            const __half2* hp = reinterpret_cast<const __half2*>(&hv);
#pragma unroll
            for (int j = 0; j < 4; j++) {
                float2 f = __half22float2(hp[j]);
                rows[lin + 2*j]     = f.x;
                rows[lin + 2*j + 1] = f.y;
            }
        } else {
#pragma unroll
            for (int j = 0; j < 8; j++) rows[lin + j] = 0.f;
        }
    }
    __syncthreads();

    const int wo = tid & 31;
    const int tg = tid >> 5;
    const int ix0 = wo * 2 - 1;

    float conv[8];
#pragma unroll
    for (int j = 0; j < 8; j++) {
        int cg = tg * 8 + j;
        float a = dw_b[cg];
#pragma unroll
        for (int ky = 0; ky < 3; ky++) {
#pragma unroll
            for (int kx = 0; kx < 3; kx++) {
                int ix = ix0 + kx;
                if ((unsigned)ix < (unsigned)WW)
                    a += rows[ky * 4096 + cg * 64 + ix] * dw_w[cg * 9 + ky * 3 + kx];
            }
        }
        conv[j] = a;
    }
    __syncthreads();

    float s = 0.f;
#pragma unroll
    for (int j = 0; j < 8; j++) s += conv[j];
    red[tg * 33 + wo] = s;
    __syncthreads();
    float mu = 0.f;
#pragma unroll
    for (int t = 0; t < 8; t++) mu += red[t * 33 + wo];
    mu *= (1.f / 64.f);
    __syncthreads();

    float s2 = 0.f;
#pragma unroll
    for (int j = 0; j < 8; j++) { float d = conv[j] - mu; s2 += d * d; }
    red[tg * 33 + wo] = s2;
    __syncthreads();
    float var = 0.f;
#pragma unroll
    for (int t = 0; t < 8; t++) var += red[t * 33 + wo];
    var *= (1.f / 64.f);
    float rstd = rsqrtf(var + 1e-5f);
    __syncthreads();

    float p0p = 0.f, p1p = 0.f;
#pragma unroll
    for (int j = 0; j < 8; j++) {
        int cg = tg * 8 + j;
        float y  = (conv[j] - mu) * rstd * ln_g[cg] + ln_b[cg];
        float ge = 0.5f * y * (1.f + erff(y * 0.70710678118654752f));
        p0p += ge * pw_w[cg];
        p1p += ge * pw_w[CG + cg];
    }
    red[tg * 33 + wo] = p0p;
    __syncthreads();
    float p0 = 0.f;
#pragma unroll
    for (int t = 0; t < 8; t++) p0 += red[t * 33 + wo];
    __syncthreads();
    red[tg * 33 + wo] = p1p;
    __syncthreads();
    if (tg == 0) {
        float p1 = 0.f;
#pragma unroll
        for (int t = 0; t < 8; t++) p1 += red[t * 33 + wo];

        float offy = tanhf(p0) * (2.0f / (float)HK);
        float offx = tanhf(p1) * (2.0f / (float)WK);
        float ref_y = (0.5f + (float)ho) * (2.f / (HK - 1.f)) - 1.f;
        float ref_x = (0.5f + (float)wo) * (2.f / (WK - 1.f)) - 1.f;
        float gx = ((offx + ref_x) + 1.f) * 0.5f * (WW - 1);
        float gy = ((offy + ref_y) + 1.f) * 0.5f * (HH - 1);

        float x0f = floorf(gx), y0f = floorf(gy);
        float wx = gx - x0f, wy = gy - y0f;
        int x0 = (int)x0f, y0 = (int)y0f;
        int x1 = x0 + 1, y1 = y0 + 1;
        float vx0 = (x0 >= 0 && x0 <= WW-1) ? 1.f : 0.f;
        float vx1 = (x1 >= 0 && x1 <= WW-1) ? 1.f : 0.f;
        float vy0 = (y0 >= 0 && y0 <= HH-1) ? 1.f : 0.f;
        float vy1 = (y1 >= 0 && y1 <= HH-1) ? 1.f : 0.f;
        int x0c = min(max(x0, 0), WW-1), x1c = min(max(x1, 0), WW-1);
        int y0c = min(max(y0, 0), HH-1), y1c = min(max(y1, 0), HH-1);

        float4 w;
        w.x = (1.f - wx) * (1.f - wy) * vx0 * vy0;
        w.y = wx * (1.f - wy) * vx1 * vy0;
        w.z = (1.f - wx) * wy * vx0 * vy1;
        w.w = wx * wy * vx1 * vy1;
        int4 id;
        id.x = y0c * WW + x0c; id.y = y0c * WW + x1c;
        id.z = y1c * WW + x0c; id.w = y1c * WW + x1c;

        size_t sIdx = (size_t)bg * NS + ho * WK + wo;
        w4[sIdx] = w;
        i4[sIdx] = id;
    }
}

// ---------------------------------------------------------------------------
// Bilinear sampling from precomputed meta.
// ---------------------------------------------------------------------------
__global__ void __launch_bounds__(256) sample_kernel(
    const float* __restrict__ feat,
    const float4* __restrict__ w4, const int4* __restrict__ i4,
    __half* __restrict__ xs)
{
    __shared__ float plane[HW];        // 16KB

    const int cg = blockIdx.x;
    const int bg = blockIdx.y;
    const int b = bg >> 2, g = bg & 3;
    const int tid = threadIdx.x;

    const float* fc = feat + (size_t)(b * CC + g * CG + cg) * HW;
#pragma unroll
    for (int l = 0; l < 4; l++) {
        int i = (tid + l * 256) * 4;
        *reinterpret_cast<float4*>(&plane[i]) = *reinterpret_cast<const float4*>(&fc[i]);
    }
    __syncthreads();

    const float4* wb = w4 + (size_t)bg * NS;
    const int4*   ib = i4 + (size_t)bg * NS;
    __half* xbase = &xs[(size_t)(bg * CG + cg) * NS];
#pragma unroll
    for (int i = 0; i < 4; i++) {
        int s = tid + i * 256;
        float4 w = wb[s];
        int4  id = ib[s];
        float acc = w.x * plane[id.x] + w.y * plane[id.y]
                  + w.z * plane[id.z] + w.w * plane[id.w];
        xbase[s] = __float2half_rn(acc);
    }
}

// ---------------------------------------------------------------------------
// Tensor-core flash attention (R10 version, unchanged).
// ---------------------------------------------------------------------------
__global__ void __launch_bounds__(256) attn_mma_kernel(
    const __half* __restrict__ qc, const __half* __restrict__ kh,
    const __half* __restrict__ vh, __half* __restrict__ out)
{
    __shared__ __half Qb[5120];          // [32][136] Q in; [128][40] O out
    __shared__ __half Ks[2][32][72];
    __shared__ __half Vs[2][32][72];

    const int tid  = threadIdx.x;
    const int lane = tid & 31;
    const int warp = tid >> 5;
    const int bh = blockIdx.y;
    const int b = bh >> 3, h = bh & 7;
    const int m0 = blockIdx.x * 128;

    const __half* qbase = qc + (size_t)(b * CC + h * HC) * HW;
    const __half* kbase = kh + (size_t)(b * CC + h * HC) * NS;
    const __half* vbase = vh + (size_t)(b * CC + h * HC) * NS;

    const int sc = tid >> 3;
    const int snn = (tid & 7) * 8;
    auto stage = [&](int chunk, int buf) {
        int n0 = chunk * 64;
        cp16(&Ks[buf][sc][snn], &kbase[(size_t)sc * NS + n0 + snn]);
        cp16(&Vs[buf][sc][snn], &vbase[(size_t)sc * NS + n0 + snn]);
    };

    stage(0, 0); cp_commit();

    {
        int row = tid >> 3;
        int col = (tid & 7) * 16;
        const __half* src = &qbase[(size_t)row * HW + m0 + col];
        *reinterpret_cast<uint4*>(&Qb[row * 136 + col])     = *reinterpret_cast<const uint4*>(src);
        *reinterpret_cast<uint4*>(&Qb[row * 136 + col + 8]) = *reinterpret_cast<const uint4*>(src + 8);
    }
    __syncthreads();

    unsigned int qf[2][4];
    {
        int c_sub = ((lane >> 4) << 3) + (lane & 7);
        int m_sub = ((lane >> 3) & 1) << 3;
#pragma unroll
        for (int ks = 0; ks < 2; ks++) {
            unsigned int addr = (unsigned int)__cvta_generic_to_shared(
                &Qb[(ks * 16 + c_sub) * 136 + warp * 16 + m_sub]);
            asm volatile("ldmatrix.sync.aligned.m8n8.x4.trans.shared.b16 {%0,%1,%2,%3},[%4];"
                         : "=r"(qf[ks][0]), "=r"(qf[ks][1]), "=r"(qf[ks][2]), "=r"(qf[ks][3])
                         : "r"(addr));
        }
        __half2 sc2 = __float2half2_rn(SCALE_LOG2E);
#pragma unroll
        for (int ks = 0; ks < 2; ks++)
#pragma unroll
            for (int r = 0; r < 4; r++) {
                __half2 v = *reinterpret_cast<__half2*>(&qf[ks][r]);
                v = __hmul2(v, sc2);
                qf[ks][r] = *reinterpret_cast<unsigned int*>(&v);
            }
    }

    float o[4][4];
#pragma unroll
    for (int cf = 0; cf < 4; cf++)
#pragma unroll
        for (int r = 0; r < 4; r++) o[cf][r] = 0.f;
    float d0 = 0.f, d1 = 0.f;

    const int NC = NS / 64;
    for (int chunk = 0; chunk < NC; chunk++) {
        const int buf = chunk & 1;
        if (chunk + 1 < NC) { stage(chunk + 1, buf ^ 1); cp_commit(); cp_wait<1>(); }
        else                { cp_wait<0>(); }
        __syncthreads();

        float sf[8][4];
#pragma unroll
        for (int nf = 0; nf < 8; nf++)
#pragma unroll
            for (int r = 0; r < 4; r++) sf[nf][r] = 0.f;
#pragma unroll
        for (int ks = 0; ks < 2; ks++) {
#pragma unroll
            for (int ng = 0; ng < 4; ng++) {
                unsigned int b0, b1, b2, b3;
                unsigned int addr = (unsigned int)__cvta_generic_to_shared(
                    &Ks[buf][ks * 16 + (lane & 15)][ng * 16 + ((lane >> 4) << 3)]);
                asm volatile("ldmatrix.sync.aligned.m8n8.x4.trans.shared.b16 {%0,%1,%2,%3},[%4];"
                             : "=r"(b0), "=r"(b1), "=r"(b2), "=r"(b3) : "r"(addr));
                asm volatile(
                    "mma.sync.aligned.m16n8k16.row.col.f32.f16.f16.f32 "
                    "{%0,%1,%2,%3},{%4,%5,%6,%7},{%8,%9},{%0,%1,%2,%3};"
                    : "+f"(sf[2*ng][0]), "+f"(sf[2*ng][1]), "+f"(sf[2*ng][2]), "+f"(sf[2*ng][3])
                    : "r"(qf[ks][0]), "r"(qf[ks][1]), "r"(qf[ks][2]), "r"(qf[ks][3]),
                      "r"(b0), "r"(b1));
                asm volatile(
                    "mma.sync.aligned.m16n8k16.row.col.f32.f16.f16.f32 "
                    "{%0,%1,%2,%3},{%4,%5,%6,%7},{%8,%9},{%0,%1,%2,%3};"
                    : "+f"(sf[2*ng+1][0]), "+f"(sf[2*ng+1][1]), "+f"(sf[2*ng+1][2]), "+f"(sf[2*ng+1][3])
                    : "r"(qf[ks][0]), "r"(qf[ks][1]), "r"(qf[ks][2]), "r"(qf[ks][3]),
                      "r"(b2), "r"(b3));
            }
        }

        unsigned int pa[4][4];
#pragma unroll
        for (int j = 0; j < 4; j++) {
            float e0 = exp2f(sf[2*j][0]);
            float e1 = exp2f(sf[2*j][1]);
            float e2 = exp2f(sf[2*j][2]);
            float e3 = exp2f(sf[2*j][3]);
            float f0 = exp2f(sf[2*j+1][0]);
            float f1 = exp2f(sf[2*j+1][1]);
            float f2 = exp2f(sf[2*j+1][2]);
            float f3 = exp2f(sf[2*j+1][3]);
            d0 += (e0 + e1) + (f0 + f1);
            d1 += (e2 + e3) + (f2 + f3);
            __half2 h0 = __floats2half2_rn(e0, e1);
            __half2 h1 = __floats2half2_rn(e2, e3);
            __half2 h2 = __floats2half2_rn(f0, f1);
            __half2 h3 = __floats2half2_rn(f2, f3);
            pa[j][0] = *reinterpret_cast<unsigned int*>(&h0);
            pa[j][1] = *reinterpret_cast<unsigned int*>(&h1);
            pa[j][2] = *reinterpret_cast<unsigned int*>(&h2);
            pa[j][3] = *reinterpret_cast<unsigned int*>(&h3);
        }

#pragma unroll
        for (int ks2 = 0; ks2 < 4; ks2++) {
#pragma unroll
            for (int cg2 = 0; cg2 < 2; cg2++) {
                unsigned int b0, b1, b2, b3;
                unsigned int addr = (unsigned int)__cvta_generic_to_shared(
                    &Vs[buf][cg2 * 16 + ((lane >> 4) << 3) + (lane & 7)]
                            [ks2 * 16 + ((lane >> 3) & 1) * 8]);
                asm volatile("ldmatrix.sync.aligned.m8n8.x4.shared.b16 {%0,%1,%2,%3},[%4];"
                             : "=r"(b0), "=r"(b1), "=r"(b2), "=r"(b3) : "r"(addr));
                asm volatile(
                    "mma.sync.aligned.m16n8k16.row.col.f32.f16.f16.f32 "
                    "{%0,%1,%2,%3},{%4,%5,%6,%7},{%8,%9},{%0,%1,%2,%3};"
                    : "+f"(o[2*cg2][0]), "+f"(o[2*cg2][1]), "+f"(o[2*cg2][2]), "+f"(o[2*cg2][3])
                    : "r"(pa[ks2][0]), "r"(pa[ks2][1]), "r"(pa[ks2][2]), "r"(pa[ks2][3]),
                      "r"(b0), "r"(b1));
                asm volatile(
                    "mma.sync.aligned.m16n8k16.row.col.f32.f16.f16.f32 "
                    "{%0,%1,%2,%3},{%4,%5,%6,%7},{%8,%9},{%0,%1,%2,%3};"
                    : "+f"(o[2*cg2+1][0]), "+f"(o[2*cg2+1][1]), "+f"(o[2*cg2+1][2]), "+f"(o[2*cg2+1][3])
                    : "r"(pa[ks2][0]), "r"(pa[ks2][1]), "r"(pa[ks2][2]), "r"(pa[ks2][3]),
                      "r"(b2), "r"(b3));
            }
        }
        __syncthreads();
    }

    d0 += __shfl_xor_sync(0xffffffffu, d0, 1);
    d0 += __shfl_xor_sync(0xffffffffu, d0, 2);
    d1 += __shfl_xor_sync(0xffffffffu, d1, 1);
    d1 += __shfl_xor_sync(0xffffffffu, d1, 2);
    float inv0 = 1.f / d0, inv1 = 1.f / d1;

    __syncthreads();
#pragma unroll
    for (int cf = 0; cf < 4; cf++) {
        int r = warp * 16 + (lane >> 2);
        int c = cf * 8 + (lane & 3) * 2;
        *reinterpret_cast<__half2*>(&Qb[r * 40 + c]) =
            __floats2half2_rn(o[cf][0] * inv0, o[cf][1] * inv0);
        *reinterpret_cast<__half2*>(&Qb[(r + 8) * 40 + c]) =
            __floats2half2_rn(o[cf][2] * inv1, o[cf][3] * inv1);
    }
    __syncthreads();

    {
        int c  = tid >> 3;
        int mb = (tid & 7) * 16;
        __half tmp[16];
#pragma unroll
        for (int j = 0; j < 16; j++) tmp[j] = Qb[(mb + j) * 40 + c];
        __half* dst = &out[((size_t)(b * CC + h * HC + c)) * HW + m0 + mb];
        *reinterpret_cast<uint4*>(dst)     = *reinterpret_cast<uint4*>(&tmp[0]);
        *reinterpret_cast<uint4*>(dst + 8) = *reinterpret_cast<uint4*>(&tmp[8]);
    }
}

// ---------------------------------------------------------------------------
extern "C" void kernel_launch(void* const* d_in, const int* in_sizes, int n_in,
                              void* d_out, int out_size)
{
    (void)in_sizes; (void)n_in; (void)out_size;
    const float* feat = (const float*)d_in[1];
    const float* dw_w = (const float*)d_in[2];
    const float* dw_b = (const float*)d_in[3];
    const float* lng  = (const float*)d_in[4];
    const float* lnb  = (const float*)d_in[5];
    const float* pw   = (const float*)d_in[6];
    const float* qw   = (const float*)d_in[7];
    const float* qb   = (const float*)d_in[8];
    const float* kw   = (const float*)d_in[9];
    const float* kb   = (const float*)d_in[10];
    const float* vw   = (const float*)d_in[11];
    const float* vb   = (const float*)d_in[12];
    const float* ow   = (const float*)d_in[13];
    const float* ob   = (const float*)d_in[14];
    float* out = (float*)d_out;

    float4* gw4; int4* gi4;
    __half *gqc, *gkh, *gvh, *gxsh, *gah;
    cudaGetSymbolAddress((void**)&gqc, g_qc);
    cudaGetSymbolAddress((void**)&gw4, g_w4);
    cudaGetSymbolAddress((void**)&gi4, g_i4);
    cudaGetSymbolAddress((void**)&gkh, g_kh);
    cudaGetSymbolAddress((void**)&gvh, g_vh);
    cudaGetSymbolAddress((void**)&gxsh, g_xs_h);
    cudaGetSymbolAddress((void**)&gah, g_attn_h);

    // 1) q projection
    hgemm_qproj<<<dim3(HW/128, CC/128, BB), 256>>>(qw, feat, qb, gqc);
    // 2) offset field (bilinear meta) then sampling
    offset_field_kernel<<<dim3(HK, BB*GG), 256>>>(gqc, dw_w, dw_b, lng, lnb, pw, gw4, gi4);
    sample_kernel<<<dim3(CG, BB*GG), 256>>>(feat, gw4, gi4, gxsh);
    // 3) k, v projections
    hgemm_kv_h<<<dim3(NS/128, CC/128, BB*2), 256>>>(kw, vw, kb, vb, gxsh, gkh, gvh);
    // 4) tensor-core flash attention
    attn_mma_kernel<<<dim3(HW/128, BH), 256>>>(gqc, gkh, gvh, gah);
    // 5) output projection
    hgemm_oproj<<<dim3(HW/128, CC/128, BB), 256>>>(ow, gah, ob, out);
}

// round 16
// speedup vs baseline: 1.1255x; 1.0170x over previous
#include <cuda_runtime.h>
#include <cuda_fp16.h>
#include <cstdint>
#include <math.h>

// Problem constants
#define BB 4
#define CC 256
#define HH 64
#define WW 64
#define GG 4
#define HEADS 8
#define BH (BB*HEADS)  // 32
#define CG 64          // C/G
#define HC 32          // C/HEADS
#define HW (HH*WW)     // 4096
#define HK 32
#define WK 32
#define NS (HK*WK)     // 1024
#define SCALE_LOG2E 0.25501650770101956f   // HC^-0.5 * log2(e)

// Scratch (device globals; no runtime allocation allowed)
__device__ __half g_qc    [BB*CC*HW];   // q half [b][C][HW]
__device__ __half g_kh    [BB*CC*NS];
__device__ __half g_vh    [BB*CC*NS];
__device__ __half g_xs_h  [BB*CC*NS];
__device__ __half g_attn_h[BB*CC*HW];
__device__ float4 g_w4    [BB*GG*NS];   // bilinear weights (valid-folded)
__device__ int4   g_i4    [BB*GG*NS];   // clamped plane indices
__device__ __half g_wq_h  [CC*CC];
__device__ __half g_wk_h  [CC*CC];
__device__ __half g_wv_h  [CC*CC];
__device__ __half g_wo_h  [CC*CC];

// ---------------------------------------------------------------------------
__device__ __forceinline__ void cp16(void* s, const void* g)
{
    unsigned int saddr = (unsigned int)__cvta_generic_to_shared(s);
    asm volatile("cp.async.cg.shared.global [%0],[%1],16;" :: "r"(saddr), "l"(g));
}
__device__ __forceinline__ void cp_commit() { asm volatile("cp.async.commit_group;"); }
template<int N> __device__ __forceinline__ void cp_wait()
{ asm volatile("cp.async.wait_group %0;" :: "n"(N)); }

// ---------------------------------------------------------------------------
// 4 weight matrices fp32->fp16 in one launch
// ---------------------------------------------------------------------------
__global__ void f2h_weights(const float* __restrict__ w0, const float* __restrict__ w1,
                            const float* __restrict__ w2, const float* __restrict__ w3,
                            __half* __restrict__ y0, __half* __restrict__ y1,
                            __half* __restrict__ y2, __half* __restrict__ y3)
{
    int i = (blockIdx.x * blockDim.x + threadIdx.x) * 4;
    const float* src; __half* dst;
    int which = i / (CC*CC);
    int off = i - which * (CC*CC);
    switch (which) {
        case 0: src = w0; dst = y0; break;
        case 1: src = w1; dst = y1; break;
        case 2: src = w2; dst = y2; break;
        default: src = w3; dst = y3; break;
    }
    float4 v = *reinterpret_cast<const float4*>(src + off);
    *reinterpret_cast<__half2*>(dst + off)     = __floats2half2_rn(v.x, v.y);
    *reinterpret_cast<__half2*>(dst + off + 2) = __floats2half2_rn(v.z, v.w);
}

// ---------------------------------------------------------------------------
// fp16 TC GEMM with bias (BM=128, BN=128, BK=32). A (half weights) staged via
// cp.async; B via cp.async when half, else fp32 register distance-2 convert.
// MODE 0: fp32 out. MODE 1: half out.
// ---------------------------------------------------------------------------
template <int MODE, bool BF32>
__device__ __forceinline__ void hgemm_body(
    const __half* __restrict__ A,
    const void* __restrict__ BxV,
    const float*  __restrict__ bias,
    void* __restrict__ Yv,
    int N, int m0, int n0)
{
    __shared__ __half As[2][128][40];
    __shared__ __half Bs[2][32][136];

    const int tid  = threadIdx.x;
    const int lane = tid & 31;
    const int warp = tid >> 5;
    const int wm = warp & 1;
    const int wn = warp >> 1;

    float acc[4][4][4];
#pragma unroll
    for (int mt = 0; mt < 4; mt++)
#pragma unroll
        for (int nt = 0; nt < 4; nt++)
#pragma unroll
            for (int r = 0; r < 4; r++) acc[mt][nt][r] = 0.f;

    auto cpStageA = [&](int kt, int buf) {
#pragma unroll
        for (int l = 0; l < 2; l++) {
            int lin = tid + l * 256;
            int r  = lin >> 2;
            int kg = (lin & 3) << 3;
            cp16(&As[buf][r][kg], &A[(size_t)(m0 + r) * CC + kt * 32 + kg]);
        }
    };
    auto cpStageB = [&](int kt, int buf) {
#pragma unroll
        for (int l = 0; l < 2; l++) {
            int lin = tid + l * 256;
            int r  = lin >> 4;
            int nn = (lin & 15) << 3;
            cp16(&Bs[buf][r][nn],
                 &((const __half*)BxV)[(size_t)(kt * 32 + r) * N + n0 + nn]);
        }
    };
    auto cvt8 = [](const float* src, uint4* dst) {
        float4 a = *reinterpret_cast<const float4*>(src);
        float4 b = *reinterpret_cast<const float4*>(src + 4);
        __half2 h[4];
        h[0] = __floats2half2_rn(a.x, a.y);
        h[1] = __floats2half2_rn(a.z, a.w);
        h[2] = __floats2half2_rn(b.x, b.y);
        h[3] = __floats2half2_rn(b.z, b.w);
        *dst = *reinterpret_cast<uint4*>(h);
    };
    auto loadBf = [&](int kt, uint4* pb) {
#pragma unroll
        for (int l = 0; l < 2; l++) {
            int lin = tid + l * 256;
            int r  = lin >> 4;
            int nn = (lin & 15) << 3;
            cvt8((const float*)BxV + (size_t)(kt * 32 + r) * N + n0 + nn, &pb[l]);
        }
    };
    auto storeBf = [&](int buf, uint4* pb) {
#pragma unroll
        for (int l = 0; l < 2; l++) {
            int lin = tid + l * 256;
            int r  = lin >> 4;
            int nn = (lin & 15) << 3;
            *reinterpret_cast<uint4*>(&Bs[buf][r][nn]) = pb[l];
        }
    };

    const int NKT = CC / 32;   // 8
    uint4 rb[2][2];

    // prologue: stages 0 and 1 in flight; BF32 reg pipeline primed to kt=2
    cpStageA(0, 0);
    if (!BF32) cpStageB(0, 0);
    cp_commit();
    if (BF32) {
        loadBf(0, rb[0]); storeBf(0, rb[0]);
        loadBf(1, rb[1]);
        loadBf(2, rb[0]);            // FIX: prime kt=2 data (was missing in R15)
    }
    cpStageA(1, 1);
    if (!BF32) cpStageB(1, 1);
    cp_commit();
    cp_wait<1>(); __syncthreads();   // stage 0 resident

    for (int kt = 0; kt < NKT; kt++) {
        const int cur = kt & 1;

#pragma unroll
        for (int ks = 0; ks < 2; ks++) {
            unsigned int af[4][4];
#pragma unroll
            for (int mt = 0; mt < 4; mt++) {
                int row = wm * 64 + mt * 16 + (lane & 15);
                int col = ks * 16 + ((lane >> 4) << 3);
                unsigned int addr = (unsigned int)__cvta_generic_to_shared(&As[cur][row][col]);
                asm volatile("ldmatrix.sync.aligned.m8n8.x4.shared.b16 {%0,%1,%2,%3},[%4];"
                             : "=r"(af[mt][0]), "=r"(af[mt][1]), "=r"(af[mt][2]), "=r"(af[mt][3])
                             : "r"(addr));
            }
            unsigned int bf[4][2];
#pragma unroll
            for (int nt = 0; nt < 4; nt++) {
                int krow = ks * 16 + (lane & 15);
                int coln = wn * 32 + nt * 8;
                unsigned int addr = (unsigned int)__cvta_generic_to_shared(&Bs[cur][krow][coln]);
                asm volatile("ldmatrix.sync.aligned.m8n8.x2.trans.shared.b16 {%0,%1},[%2];"
                             : "=r"(bf[nt][0]), "=r"(bf[nt][1])
                             : "r"(addr));
            }
#pragma unroll
            for (int mt = 0; mt < 4; mt++)
#pragma unroll
                for (int nt = 0; nt < 4; nt++) {
                    asm volatile(
                        "mma.sync.aligned.m16n8k16.row.col.f32.f16.f16.f32 "
                        "{%0,%1,%2,%3},{%4,%5,%6,%7},{%8,%9},{%0,%1,%2,%3};"
                        : "+f"(acc[mt][nt][0]), "+f"(acc[mt][nt][1]),
                          "+f"(acc[mt][nt][2]), "+f"(acc[mt][nt][3])
                        : "r"(af[mt][0]), "r"(af[mt][1]), "r"(af[mt][2]), "r"(af[mt][3]),
                          "r"(bf[nt][0]), "r"(bf[nt][1]));
                }
        }

        if (kt + 1 < NKT) {
            const int ns = (kt + 1) & 1;
            if (BF32) {
                storeBf(ns, rb[ns]);                         // B for kt+1
                if (kt + 3 < NKT) loadBf(kt + 3, rb[ns]);    // prefetch B kt+3
            }
            __syncthreads();        // reads of buf cur complete before cp overwrite
            if (kt + 2 < NKT) {
                cpStageA(kt + 2, cur);
                if (!BF32) cpStageB(kt + 2, cur);
                cp_commit();
                cp_wait<1>();       // stage kt+1 resident
            } else {
                cp_wait<0>();       // drain: stage kt+1 resident
            }
            __syncthreads();
        }
    }

#pragma unroll
    for (int mt = 0; mt < 4; mt++) {
        int r0 = m0 + wm * 64 + mt * 16 + (lane >> 2);
        float b0 = bias[r0], b1 = bias[r0 + 8];
#pragma unroll
        for (int nt = 0; nt < 4; nt++) {
            int c = n0 + wn * 32 + nt * 8 + (lane & 3) * 2;
            float v0 = acc[mt][nt][0] + b0, v1 = acc[mt][nt][1] + b0;
            float v2 = acc[mt][nt][2] + b1, v3 = acc[mt][nt][3] + b1;
            if (MODE == 0) {
                float* Y = (float*)Yv;
                *reinterpret_cast<float2*>(&Y[(size_t)r0 * N + c])       = make_float2(v0, v1);
                *reinterpret_cast<float2*>(&Y[(size_t)(r0 + 8) * N + c]) = make_float2(v2, v3);
            } else {
                __half* Y = (__half*)Yv;
                *reinterpret_cast<__half2*>(&Y[(size_t)r0 * N + c])       = __floats2half2_rn(v0, v1);
                *reinterpret_cast<__half2*>(&Y[(size_t)(r0 + 8) * N + c]) = __floats2half2_rn(v2, v3);
            }
        }
    }
}

__global__ void __launch_bounds__(256) hgemm_qproj(
    const __half* __restrict__ W, const float* __restrict__ X,
    const float* __restrict__ bias, __half* __restrict__ Y)
{
    hgemm_body<1, true>(W, X + (size_t)blockIdx.z * CC * HW, bias,
                        Y + (size_t)blockIdx.z * CC * HW, HW,
                        blockIdx.y * 128, blockIdx.x * 128);
}

__global__ void __launch_bounds__(256) hgemm_oproj(
    const __half* __restrict__ W, const __half* __restrict__ X,
    const float* __restrict__ bias, float* __restrict__ Y)
{
    hgemm_body<0, false>(W, X + (size_t)blockIdx.z * CC * HW, bias,
                         Y + (size_t)blockIdx.z * CC * HW, HW,
                         blockIdx.y * 128, blockIdx.x * 128);
}

__global__ void __launch_bounds__(256) hgemm_kv_h(
    const __half* __restrict__ Wk, const __half* __restrict__ Wv,
    const float* __restrict__ bk, const float* __restrict__ bv,
    const __half* __restrict__ X, __half* __restrict__ Yk, __half* __restrict__ Yv)
{
    int z = blockIdx.z;
    int b = z >> 1;
    bool isv = z & 1;
    hgemm_body<1, false>(isv ? Wv : Wk, X + (size_t)b * CC * NS, isv ? bv : bk,
                         (isv ? Yv : Yk) + (size_t)b * CC * NS, NS,
                         blockIdx.y * 128, blockIdx.x * 128);
}

// ---------------------------------------------------------------------------
// Offset field: dwconv + LN + GELU + pointwise + tanh -> bilinear meta.
// ---------------------------------------------------------------------------
__global__ void __launch_bounds__(256) offset_field_kernel(
    const __half* __restrict__ qc,
    const float* __restrict__ dw_w, const float* __restrict__ dw_b,
    const float* __restrict__ ln_g, const float* __restrict__ ln_b,
    const float* __restrict__ pw_w,
    float4* __restrict__ w4, int4* __restrict__ i4)
{
    __shared__ float rows[3 * CG * WW];   // 48KB exactly; reused as reduction buf
    float* red = rows;                    // [8][33]: red[tg*33 + wo]

    const int ho = blockIdx.x;
    const int bg = blockIdx.y;
    const int b = bg >> 2, g = bg & 3;
    const int tid = threadIdx.x;
    const int iy0 = ho * 2 - 1;

    const __half* qbase = qc + (size_t)(b * CC + g * CG) * HW;
#pragma unroll
    for (int l = 0; l < 6; l++) {
        int lin = (tid + l * 256) * 8;
        int r   = lin >> 12;
        int rem = lin & 4095;
        int cg  = rem >> 6;
        int w   = rem & 63;
        int iy  = iy0 + r;
        if ((unsigned)iy < (unsigned)HH) {
            uint4 hv = *reinterpret_cast<const uint4*>(&qbase[(size_t)cg * HW + iy * WW + w]);
            const __half2* hp = reinterpret_cast<const __half2*>(&hv);
#pragma unroll
            for (int j = 0; j < 4; j++) {
                float2 f = __half22float2(hp[j]);
                rows[lin + 2*j]     = f.x;
                rows[lin + 2*j + 1] = f.y;
            }
        } else {
#pragma unroll
            for (int j = 0; j < 8; j++) rows[lin + j] = 0.f;
        }
    }
    __syncthreads();

    const int wo = tid & 31;
    const int tg = tid >> 5;
    const int ix0 = wo * 2 - 1;

    float conv[8];
#pragma unroll
    for (int j = 0; j < 8; j++) {
        int cg = tg * 8 + j;
        float a = dw_b[cg];
#pragma unroll
        for (int ky = 0; ky < 3; ky++) {
#pragma unroll
            for (int kx = 0; kx < 3; kx++) {
                int ix = ix0 + kx;
                if ((unsigned)ix < (unsigned)WW)
                    a += rows[ky * 4096 + cg * 64 + ix] * dw_w[cg * 9 + ky * 3 + kx];
            }
        }
        conv[j] = a;
    }
    __syncthreads();

    float s = 0.f;
#pragma unroll
    for (int j = 0; j < 8; j++) s += conv[j];
    red[tg * 33 + wo] = s;
    __syncthreads();
    float mu = 0.f;
#pragma unroll
    for (int t = 0; t < 8; t++) mu += red[t * 33 + wo];
    mu *= (1.f / 64.f);
    __syncthreads();

    float s2 = 0.f;
#pragma unroll
    for (int j = 0; j < 8; j++) { float d = conv[j] - mu; s2 += d * d; }
    red[tg * 33 + wo] = s2;
    __syncthreads();
    float var = 0.f;
#pragma unroll
    for (int t = 0; t < 8; t++) var += red[t * 33 + wo];
    var *= (1.f / 64.f);
    float rstd = rsqrtf(var + 1e-5f);
    __syncthreads();

    float p0p = 0.f, p1p = 0.f;
#pragma unroll
    for (int j = 0; j < 8; j++) {
        int cg = tg * 8 + j;
        float y  = (conv[j] - mu) * rstd * ln_g[cg] + ln_b[cg];
        float ge = 0.5f * y * (1.f + erff(y * 0.70710678118654752f));
        p0p += ge * pw_w[cg];
        p1p += ge * pw_w[CG + cg];
    }
    red[tg * 33 + wo] = p0p;
    __syncthreads();
    float p0 = 0.f;
#pragma unroll
    for (int t = 0; t < 8; t++) p0 += red[t * 33 + wo];
    __syncthreads();
    red[tg * 33 + wo] = p1p;
    __syncthreads();
    if (tg == 0) {
        float p1 = 0.f;
#pragma unroll
        for (int t = 0; t < 8; t++) p1 += red[t * 33 + wo];

        float offy = tanhf(p0) * (2.0f / (float)HK);
        float offx = tanhf(p1) * (2.0f / (float)WK);
        float ref_y = (0.5f + (float)ho) * (2.f / (HK - 1.f)) - 1.f;
        float ref_x = (0.5f + (float)wo) * (2.f / (WK - 1.f)) - 1.f;
        float gx = ((offx + ref_x) + 1.f) * 0.5f * (WW - 1);
        float gy = ((offy + ref_y) + 1.f) * 0.5f * (HH - 1);

        float x0f = floorf(gx), y0f = floorf(gy);
        float wx = gx - x0f, wy = gy - y0f;
        int x0 = (int)x0f, y0 = (int)y0f;
        int x1 = x0 + 1, y1 = y0 + 1;
        float vx0 = (x0 >= 0 && x0 <= WW-1) ? 1.f : 0.f;
        float vx1 = (x1 >= 0 && x1 <= WW-1) ? 1.f : 0.f;
        float vy0 = (y0 >= 0 && y0 <= HH-1) ? 1.f : 0.f;
        float vy1 = (y1 >= 0 && y1 <= HH-1) ? 1.f : 0.f;
        int x0c = min(max(x0, 0), WW-1), x1c = min(max(x1, 0), WW-1);
        int y0c = min(max(y0, 0), HH-1), y1c = min(max(y1, 0), HH-1);

        float4 w;
        w.x = (1.f - wx) * (1.f - wy) * vx0 * vy0;
        w.y = wx * (1.f - wy) * vx1 * vy0;
        w.z = (1.f - wx) * wy * vx0 * vy1;
        w.w = wx * wy * vx1 * vy1;
        int4 id;
        id.x = y0c * WW + x0c; id.y = y0c * WW + x1c;
        id.z = y1c * WW + x0c; id.w = y1c * WW + x1c;

        size_t sIdx = (size_t)bg * NS + ho * WK + wo;
        w4[sIdx] = w;
        i4[sIdx] = id;
    }
}

// ---------------------------------------------------------------------------
// Bilinear sampling from precomputed meta.
// ---------------------------------------------------------------------------
__global__ void __launch_bounds__(256) sample_kernel(
    const float* __restrict__ feat,
    const float4* __restrict__ w4, const int4* __restrict__ i4,
    __half* __restrict__ xs)
{
    __shared__ float plane[HW];        // 16KB

    const int cg = blockIdx.x;
    const int bg = blockIdx.y;
    const int b = bg >> 2, g = bg & 3;
    const int tid = threadIdx.x;

    const float* fc = feat + (size_t)(b * CC + g * CG + cg) * HW;
#pragma unroll
    for (int l = 0; l < 4; l++) {
        int i = (tid + l * 256) * 4;
        *reinterpret_cast<float4*>(&plane[i]) = *reinterpret_cast<const float4*>(&fc[i]);
    }
    __syncthreads();

    const float4* wb = w4 + (size_t)bg * NS;
    const int4*   ib = i4 + (size_t)bg * NS;
    __half* xbase = &xs[(size_t)(bg * CG + cg) * NS];
#pragma unroll
    for (int i = 0; i < 4; i++) {
        int s = tid + i * 256;
        float4 w = wb[s];
        int4  id = ib[s];
        float acc = w.x * plane[id.x] + w.y * plane[id.y]
                  + w.z * plane[id.z] + w.w * plane[id.w];
        xbase[s] = __float2half_rn(acc);
    }
}

// ---------------------------------------------------------------------------
// Tensor-core flash attention (champion R10 version, unchanged).
// ---------------------------------------------------------------------------
__global__ void __launch_bounds__(256) attn_mma_kernel(
    const __half* __restrict__ qc, const __half* __restrict__ kh,
    const __half* __restrict__ vh, __half* __restrict__ out)
{
    __shared__ __half Qb[5120];          // [32][136] Q in; [128][40] O out
    __shared__ __half Ks[2][32][72];
    __shared__ __half Vs[2][32][72];

    const int tid  = threadIdx.x;
    const int lane = tid & 31;
    const int warp = tid >> 5;
    const int bh = blockIdx.y;
    const int b = bh >> 3, h = bh & 7;
    const int m0 = blockIdx.x * 128;

    const __half* qbase = qc + (size_t)(b * CC + h * HC) * HW;
    const __half* kbase = kh + (size_t)(b * CC + h * HC) * NS;
    const __half* vbase = vh + (size_t)(b * CC + h * HC) * NS;

    const int sc = tid >> 3;
    const int snn = (tid & 7) * 8;
    auto stage = [&](int chunk, int buf) {
        int n0 = chunk * 64;
        cp16(&Ks[buf][sc][snn], &kbase[(size_t)sc * NS + n0 + snn]);
        cp16(&Vs[buf][sc][snn], &vbase[(size_t)sc * NS + n0 + snn]);
    };

    stage(0, 0); cp_commit();

    {
        int row = tid >> 3;
        int col = (tid & 7) * 16;
        const __half* src = &qbase[(size_t)row * HW + m0 + col];
        *reinterpret_cast<uint4*>(&Qb[row * 136 + col])     = *reinterpret_cast<const uint4*>(src);
        *reinterpret_cast<uint4*>(&Qb[row * 136 + col + 8]) = *reinterpret_cast<const uint4*>(src + 8);
    }
    __syncthreads();

    unsigned int qf[2][4];
    {
        int c_sub = ((lane >> 4) << 3) + (lane & 7);
        int m_sub = ((lane >> 3) & 1) << 3;
#pragma unroll
        for (int ks = 0; ks < 2; ks++) {
            unsigned int addr = (unsigned int)__cvta_generic_to_shared(
                &Qb[(ks * 16 + c_sub) * 136 + warp * 16 + m_sub]);
            asm volatile("ldmatrix.sync.aligned.m8n8.x4.trans.shared.b16 {%0,%1,%2,%3},[%4];"
                         : "=r"(qf[ks][0]), "=r"(qf[ks][1]), "=r"(qf[ks][2]), "=r"(qf[ks][3])
                         : "r"(addr));
        }
        __half2 sc2 = __float2half2_rn(SCALE_LOG2E);
#pragma unroll
        for (int ks = 0; ks < 2; ks++)
#pragma unroll
            for (int r = 0; r < 4; r++) {
                __half2 v = *reinterpret_cast<__half2*>(&qf[ks][r]);
                v = __hmul2(v, sc2);
                qf[ks][r] = *reinterpret_cast<unsigned int*>(&v);
            }
    }

    float o[4][4];
#pragma unroll
    for (int cf = 0; cf < 4; cf++)
#pragma unroll
        for (int r = 0; r < 4; r++) o[cf][r] = 0.f;
    float d0 = 0.f, d1 = 0.f;

    const int NC = NS / 64;
    for (int chunk = 0; chunk < NC; chunk++) {
        const int buf = chunk & 1;
        if (chunk + 1 < NC) { stage(chunk + 1, buf ^ 1); cp_commit(); cp_wait<1>(); }
        else                { cp_wait<0>(); }
        __syncthreads();

        float sf[8][4];
#pragma unroll
        for (int nf = 0; nf < 8; nf++)
#pragma unroll
            for (int r = 0; r < 4; r++) sf[nf][r] = 0.f;
#pragma unroll
        for (int ks = 0; ks < 2; ks++) {
#pragma unroll
            for (int ng = 0; ng < 4; ng++) {
                unsigned int b0, b1, b2, b3;
                unsigned int addr = (unsigned int)__cvta_generic_to_shared(
                    &Ks[buf][ks * 16 + (lane & 15)][ng * 16 + ((lane >> 4) << 3)]);
                asm volatile("ldmatrix.sync.aligned.m8n8.x4.trans.shared.b16 {%0,%1,%2,%3},[%4];"
                             : "=r"(b0), "=r"(b1), "=r"(b2), "=r"(b3) : "r"(addr));
                asm volatile(
                    "mma.sync.aligned.m16n8k16.row.col.f32.f16.f16.f32 "
                    "{%0,%1,%2,%3},{%4,%5,%6,%7},{%8,%9},{%0,%1,%2,%3};"
                    : "+f"(sf[2*ng][0]), "+f"(sf[2*ng][1]), "+f"(sf[2*ng][2]), "+f"(sf[2*ng][3])
                    : "r"(qf[ks][0]), "r"(qf[ks][1]), "r"(qf[ks][2]), "r"(qf[ks][3]),
                      "r"(b0), "r"(b1));
                asm volatile(
                    "mma.sync.aligned.m16n8k16.row.col.f32.f16.f16.f32 "
                    "{%0,%1,%2,%3},{%4,%5,%6,%7},{%8,%9},{%0,%1,%2,%3};"
                    : "+f"(sf[2*ng+1][0]), "+f"(sf[2*ng+1][1]), "+f"(sf[2*ng+1][2]), "+f"(sf[2*ng+1][3])
                    : "r"(qf[ks][0]), "r"(qf[ks][1]), "r"(qf[ks][2]), "r"(qf[ks][3]),
                      "r"(b2), "r"(b3));
            }
        }

        unsigned int pa[4][4];
#pragma unroll
        for (int j = 0; j < 4; j++) {
            float e0 = exp2f(sf[2*j][0]);
            float e1 = exp2f(sf[2*j][1]);
            float e2 = exp2f(sf[2*j][2]);
            float e3 = exp2f(sf[2*j][3]);
            float f0 = exp2f(sf[2*j+1][0]);
            float f1 = exp2f(sf[2*j+1][1]);
            float f2 = exp2f(sf[2*j+1][2]);
            float f3 = exp2f(sf[2*j+1][3]);
            d0 += (e0 + e1) + (f0 + f1);
            d1 += (e2 + e3) + (f2 + f3);
            __half2 h0 = __floats2half2_rn(e0, e1);
            __half2 h1 = __floats2half2_rn(e2, e3);
            __half2 h2 = __floats2half2_rn(f0, f1);
            __half2 h3 = __floats2half2_rn(f2, f3);
            pa[j][0] = *reinterpret_cast<unsigned int*>(&h0);
            pa[j][1] = *reinterpret_cast<unsigned int*>(&h1);
            pa[j][2] = *reinterpret_cast<unsigned int*>(&h2);
            pa[j][3] = *reinterpret_cast<unsigned int*>(&h3);
        }

#pragma unroll
        for (int ks2 = 0; ks2 < 4; ks2++) {
#pragma unroll
            for (int cg2 = 0; cg2 < 2; cg2++) {
                unsigned int b0, b1, b2, b3;
                unsigned int addr = (unsigned int)__cvta_generic_to_shared(
                    &Vs[buf][cg2 * 16 + ((lane >> 4) << 3) + (lane & 7)]
                            [ks2 * 16 + ((lane >> 3) & 1) * 8]);
                asm volatile("ldmatrix.sync.aligned.m8n8.x4.shared.b16 {%0,%1,%2,%3},[%4];"
                             : "=r"(b0), "=r"(b1), "=r"(b2), "=r"(b3) : "r"(addr));
                asm volatile(
                    "mma.sync.aligned.m16n8k16.row.col.f32.f16.f16.f32 "
                    "{%0,%1,%2,%3},{%4,%5,%6,%7},{%8,%9},{%0,%1,%2,%3};"
                    : "+f"(o[2*cg2][0]), "+f"(o[2*cg2][1]), "+f"(o[2*cg2][2]), "+f"(o[2*cg2][3])
                    : "r"(pa[ks2][0]), "r"(pa[ks2][1]), "r"(pa[ks2][2]), "r"(pa[ks2][3]),
                      "r"(b0), "r"(b1));
                asm volatile(
                    "mma.sync.aligned.m16n8k16.row.col.f32.f16.f16.f32 "
                    "{%0,%1,%2,%3},{%4,%5,%6,%7},{%8,%9},{%0,%1,%2,%3};"
                    : "+f"(o[2*cg2+1][0]), "+f"(o[2*cg2+1][1]), "+f"(o[2*cg2+1][2]), "+f"(o[2*cg2+1][3])
                    : "r"(pa[ks2][0]), "r"(pa[ks2][1]), "r"(pa[ks2][2]), "r"(pa[ks2][3]),
                      "r"(b2), "r"(b3));
            }
        }
        __syncthreads();
    }

    d0 += __shfl_xor_sync(0xffffffffu, d0, 1);
    d0 += __shfl_xor_sync(0xffffffffu, d0, 2);
    d1 += __shfl_xor_sync(0xffffffffu, d1, 1);
    d1 += __shfl_xor_sync(0xffffffffu, d1, 2);
    float inv0 = 1.f / d0, inv1 = 1.f / d1;

    __syncthreads();
#pragma unroll
    for (int cf = 0; cf < 4; cf++) {
        int r = warp * 16 + (lane >> 2);
        int c = cf * 8 + (lane & 3) * 2;
        *reinterpret_cast<__half2*>(&Qb[r * 40 + c]) =
            __floats2half2_rn(o[cf][0] * inv0, o[cf][1] * inv0);
        *reinterpret_cast<__half2*>(&Qb[(r + 8) * 40 + c]) =
            __floats2half2_rn(o[cf][2] * inv1, o[cf][3] * inv1);
    }
    __syncthreads();

    {
        int c  = tid >> 3;
        int mb = (tid & 7) * 16;
        __half tmp[16];
#pragma unroll
        for (int j = 0; j < 16; j++) tmp[j] = Qb[(mb + j) * 40 + c];
        __half* dst = &out[((size_t)(b * CC + h * HC + c)) * HW + m0 + mb];
        *reinterpret_cast<uint4*>(dst)     = *reinterpret_cast<uint4*>(&tmp[0]);
        *reinterpret_cast<uint4*>(dst + 8) = *reinterpret_cast<uint4*>(&tmp[8]);
    }
}

// ---------------------------------------------------------------------------
extern "C" void kernel_launch(void* const* d_in, const int* in_sizes, int n_in,
                              void* d_out, int out_size)
{
    (void)in_sizes; (void)n_in; (void)out_size;
    const float* feat = (const float*)d_in[1];
    const float* dw_w = (const float*)d_in[2];
    const float* dw_b = (const float*)d_in[3];
    const float* lng  = (const float*)d_in[4];
    const float* lnb  = (const float*)d_in[5];
    const float* pw   = (const float*)d_in[6];
    const float* qw   = (const float*)d_in[7];
    const float* qb   = (const float*)d_in[8];
    const float* kw   = (const float*)d_in[9];
    const float* kb   = (const float*)d_in[10];
    const float* vw   = (const float*)d_in[11];
    const float* vb   = (const float*)d_in[12];
    const float* ow   = (const float*)d_in[13];
    const float* ob   = (const float*)d_in[14];
    float* out = (float*)d_out;

    float4* gw4; int4* gi4;
    __half *gqc, *gkh, *gvh, *gxsh, *gah, *gwq, *gwk, *gwv, *gwo;
    cudaGetSymbolAddress((void**)&gqc, g_qc);
    cudaGetSymbolAddress((void**)&gw4, g_w4);
    cudaGetSymbolAddress((void**)&gi4, g_i4);
    cudaGetSymbolAddress((void**)&gkh, g_kh);
    cudaGetSymbolAddress((void**)&gvh, g_vh);
    cudaGetSymbolAddress((void**)&gxsh, g_xs_h);
    cudaGetSymbolAddress((void**)&gah, g_attn_h);
    cudaGetSymbolAddress((void**)&gwq, g_wq_h);
    cudaGetSymbolAddress((void**)&gwk, g_wk_h);
    cudaGetSymbolAddress((void**)&gwv, g_wv_h);
    cudaGetSymbolAddress((void**)&gwo, g_wo_h);

    // 0) weight conversions (half weights enable cp.async A staging)
    f2h_weights<<<(4*CC*CC/4 + 255)/256, 256>>>(qw, kw, vw, ow, gwq, gwk, gwv, gwo);

    // 1) q projection
    hgemm_qproj<<<dim3(HW/128, CC/128, BB), 256>>>(gwq, feat, qb, gqc);
    // 2) offset field (bilinear meta) then sampling
    offset_field_kernel<<<dim3(HK, BB*GG), 256>>>(gqc, dw_w, dw_b, lng, lnb, pw, gw4, gi4);
    sample_kernel<<<dim3(CG, BB*GG), 256>>>(feat, gw4, gi4, gxsh);
    // 3) k, v projections
    hgemm_kv_h<<<dim3(NS/128, CC/128, BB*2), 256>>>(gwk, gwv, kb, vb, gxsh, gkh, gvh);
    // 4) tensor-core flash attention
    attn_mma_kernel<<<dim3(HW/128, BH), 256>>>(gqc, gkh, gvh, gah);
    // 5) output projection
    hgemm_oproj<<<dim3(HW/128, CC/128, BB), 256>>>(gwo, gah, ob, out);
}